// round 5
// baseline (speedup 1.0000x reference)
#include <cuda_runtime.h>
#include <math_constants.h>

#define BB 8
#define CC 512
#define NN 1024
#define HH 8
#define DD 64

// Scratch (allocation-free: __device__ globals)
__device__ float  g_q[BB*HH*NN*DD];     // 16 MB: Q[b][h][n][d]
__device__ float  g_k[BB*HH*NN*DD];     // 16 MB: K[b][h][n][d]
__device__ float  g_attn[BB*NN*NN];     // 32 MB: sum over heads of softmax rows
__device__ double g_rinv[BB*NN];        // 1 / row-sum of exp(attn/256)
__device__ double g_ksc[BB*NN];         // key_scores accumulators (fp64)
__device__ float  g_mp[BB*CC];          // max-pooled (B, C)

// exp(xv) for xv in [0, 1/32]: degree-6 Taylor, |err| <= (1/32)^7/5040 ~ 6e-15
__device__ __forceinline__ double exp_small(double xv) {
    double p = 1.0 / 720.0;
    p = fma(p, xv, 1.0 / 120.0);
    p = fma(p, xv, 1.0 / 24.0);
    p = fma(p, xv, 1.0 / 6.0);
    p = fma(p, xv, 0.5);
    p = fma(p, xv, 1.0);
    p = fma(p, xv, 1.0);
    return p;
}

// ---------------------------------------------------------------------------
// Kernel 1: fused Q/K projection.
// ---------------------------------------------------------------------------
__global__ __launch_bounds__(256) void proj_kernel(const float* __restrict__ x,
                                                   const float* __restrict__ W,
                                                   const float* __restrict__ bias) {
    __shared__ float As[16][65];
    __shared__ float Bs[16][65];
    int tid = threadIdx.x;
    int tx = tid & 15, ty = tid >> 4;
    int j0 = blockIdx.x * 64;
    int m0 = blockIdx.y * 64;
    int b  = m0 >> 10;
    int n0 = m0 & 1023;
    const float* xb = x + (size_t)b * CC * NN;

    float acc[4][4];
    #pragma unroll
    for (int i = 0; i < 4; i++)
        #pragma unroll
        for (int j = 0; j < 4; j++) acc[i][j] = 0.f;

    for (int kb = 0; kb < CC; kb += 16) {
        #pragma unroll
        for (int p = 0; p < 4; p++) {
            int e = tid + p * 256;
            int kk = e >> 6, m = e & 63;
            As[kk][m] = xb[(kb + kk) * NN + n0 + m];
        }
        #pragma unroll
        for (int p = 0; p < 4; p++) {
            int e = tid + p * 256;
            int kk = e & 15, jl = e >> 4;
            Bs[kk][jl] = W[(size_t)(j0 + jl) * CC + kb + kk];
        }
        __syncthreads();
        #pragma unroll
        for (int kk = 0; kk < 16; kk++) {
            float a[4], bv[4];
            #pragma unroll
            for (int i = 0; i < 4; i++) a[i] = As[kk][ty * 4 + i];
            #pragma unroll
            for (int j = 0; j < 4; j++) bv[j] = Bs[kk][tx + j * 16];
            #pragma unroll
            for (int i = 0; i < 4; i++)
                #pragma unroll
                for (int j = 0; j < 4; j++) acc[i][j] += a[i] * bv[j];
        }
        __syncthreads();
    }

    #pragma unroll
    for (int j = 0; j < 4; j++) {
        int jg = j0 + tx + j * 16;
        float bsv = bias[jg];
        int head = (jg & 511) >> 6;
        int dd   = jg & 63;
        float* dst = (jg < 512) ? g_q : g_k;
        #pragma unroll
        for (int i = 0; i < 4; i++) {
            int n = n0 + ty * 4 + i;
            dst[((size_t)(b * HH + head) * NN + n) * DD + dd] = acc[i][j] + bsv;
        }
    }
}

// ---------------------------------------------------------------------------
// Kernel 2: scores + per-head softmax + head accumulation.
// At h==7 (final head) the completed attn row value is in registers: fuse the
// w2 row-sum (pass A): rowsum = sum_k exp(attn/256), store 1/rowsum. Warp-
// local only (shuffles), no extra barriers; DFMA overlaps the FMA-bound GEMM.
// ---------------------------------------------------------------------------
#define SMEM2 ((2080 + 8320 + 32 * 1024) * 4)

__global__ __launch_bounds__(256) void attn_kernel() {
    extern __shared__ float sm[];
    float* Qs = sm;               // [32][65]
    float* Ks = sm + 2080;        // [128][65]
    float* S  = sm + 2080 + 8320; // [32][1024]

    int tid = threadIdx.x;
    int b  = blockIdx.x >> 5;
    int q0 = (blockIdx.x & 31) << 5;
    int tx = tid & 31, ty = tid >> 5;

    for (int h = 0; h < HH; h++) {
        const float* Qg = g_q + ((size_t)(b * HH + h) * NN + q0) * DD;
        const float* Kg = g_k + (size_t)(b * HH + h) * NN * DD;

        #pragma unroll
        for (int p = 0; p < 8; p++) {
            int e = tid + p * 256;
            int r = e >> 6, dd = e & 63;
            Qs[r * 65 + dd] = Qg[r * DD + dd];
        }

        for (int kt = 0; kt < 8; kt++) {
            int k0 = kt * 128;
            __syncthreads();
            #pragma unroll
            for (int p = 0; p < 32; p++) {
                int e = tid + p * 256;
                int r = e >> 6, dd = e & 63;
                Ks[r * 65 + dd] = Kg[(k0 + r) * DD + dd];
            }
            __syncthreads();

            float acc[4][4] = {};
            #pragma unroll
            for (int kk = 0; kk < 64; kk++) {
                float a[4], bv[4];
                #pragma unroll
                for (int i = 0; i < 4; i++) a[i] = Qs[(ty * 4 + i) * 65 + kk];
                #pragma unroll
                for (int j = 0; j < 4; j++) bv[j] = Ks[(tx + j * 32) * 65 + kk];
                #pragma unroll
                for (int i = 0; i < 4; i++)
                    #pragma unroll
                    for (int j = 0; j < 4; j++) acc[i][j] += a[i] * bv[j];
            }
            #pragma unroll
            for (int i = 0; i < 4; i++)
                #pragma unroll
                for (int j = 0; j < 4; j++)
                    S[(ty * 4 + i) * 1024 + k0 + tx + j * 32] = acc[i][j] * 0.125f;
        }
        __syncthreads();

        #pragma unroll
        for (int r = 0; r < 4; r++) {
            int row = ty * 4 + r;
            float* Sr = S + row * 1024;
            float m = -CUDART_INF_F;
            for (int c = tx; c < 1024; c += 32) m = fmaxf(m, Sr[c]);
            #pragma unroll
            for (int o = 16; o; o >>= 1) m = fmaxf(m, __shfl_xor_sync(~0u, m, o));
            float s = 0.f;
            for (int c = tx; c < 1024; c += 32) { float e = expf(Sr[c] - m); Sr[c] = e; s += e; }
            #pragma unroll
            for (int o = 16; o; o >>= 1) s += __shfl_xor_sync(~0u, s, o);
            float inv = 1.f / s;
            float* gp = g_attn + ((size_t)(b * NN + q0 + row)) * NN;
            if (h == 0) {
                for (int c = tx; c < 1024; c += 32) gp[c] = Sr[c] * inv;
            } else if (h < 7) {
                for (int c = tx; c < 1024; c += 32) gp[c] += Sr[c] * inv;
            } else {
                double s2 = 0.0;
                for (int c = tx; c < 1024; c += 32) {
                    float fin = gp[c] + Sr[c] * inv;
                    gp[c] = fin;
                    s2 += exp_small((double)fin * (1.0 / 256.0));
                }
                #pragma unroll
                for (int o = 16; o; o >>= 1) s2 += __shfl_xor_sync(~0u, s2, o);
                if (tx == 0) g_rinv[b * NN + q0 + row] = 1.0 / s2;
            }
        }
        __syncthreads();
    }
}

// ---------------------------------------------------------------------------
// Kernel 3: column accumulation (pass B). Barrier-free, high-MLP stream of
// g_attn; each thread owns 4 fixed columns over a 64-row q-chunk, one fp64
// atomicAdd per column at the end.
// ---------------------------------------------------------------------------
__global__ void zero_ks_kernel() {
    g_ksc[blockIdx.x * 1024 + threadIdx.x] = 0.0;
}

__global__ __launch_bounds__(256) void colsum_kernel() {
    int b  = blockIdx.x >> 4;
    int q0 = (blockIdx.x & 15) << 6;
    int tid = threadIdx.x;
    const float* base = g_attn + ((size_t)b * NN + q0) * NN;
    const double* rinv = g_rinv + b * NN + q0;

    double acc[4] = {0.0, 0.0, 0.0, 0.0};
    #pragma unroll 2
    for (int q = 0; q < 64; q++) {
        const float* row = base + (size_t)q * NN;
        double inv = rinv[q];
        float v[4];
        #pragma unroll
        for (int j = 0; j < 4; j++) v[j] = row[tid + j * 256];
        #pragma unroll
        for (int j = 0; j < 4; j++)
            acc[j] = fma(exp_small((double)v[j] * (1.0 / 256.0)), inv, acc[j]);
    }
    #pragma unroll
    for (int j = 0; j < 4; j++)
        atomicAdd(&g_ksc[b * NN + tid + j * 256], acc[j] * (1.0 / 1024.0));
}

// ---------------------------------------------------------------------------
// Kernel 4: top-8 per batch, FP32 compares (matches reference's fp32
// quantization of key_scores; ties broken by lower index), then max-pool.
// ---------------------------------------------------------------------------
__global__ __launch_bounds__(256) void topk_kernel(const float* __restrict__ x) {
    __shared__ float bvv[8];
    __shared__ int   bii[8];
    __shared__ int   sel[8];
    __shared__ int   sbi;
    int b = blockIdx.x;
    int tid = threadIdx.x;
    int lane = tid & 31, warp = tid >> 5;

    float v[4]; int idx[4];
    #pragma unroll
    for (int j = 0; j < 4; j++) {
        idx[j] = tid + j * 256;
        v[j] = (float)g_ksc[b * NN + idx[j]];   // round-to-nearest fp32, like ref
    }

    for (int it = 0; it < 8; it++) {
        float mv = v[0]; int mi = idx[0];
        #pragma unroll
        for (int j = 1; j < 4; j++)
            if (v[j] > mv || (v[j] == mv && idx[j] < mi)) { mv = v[j]; mi = idx[j]; }
        #pragma unroll
        for (int o = 16; o; o >>= 1) {
            float ov = __shfl_xor_sync(~0u, mv, o);
            int   oi = __shfl_xor_sync(~0u, mi, o);
            if (ov > mv || (ov == mv && oi < mi)) { mv = ov; mi = oi; }
        }
        if (lane == 0) { bvv[warp] = mv; bii[warp] = mi; }
        __syncthreads();
        if (tid == 0) {
            float m2 = bvv[0]; int i2 = bii[0];
            for (int w = 1; w < 8; w++)
                if (bvv[w] > m2 || (bvv[w] == m2 && bii[w] < i2)) { m2 = bvv[w]; i2 = bii[w]; }
            sel[it] = i2; sbi = i2;
        }
        __syncthreads();
        int si = sbi;
        #pragma unroll
        for (int j = 0; j < 4; j++) if (idx[j] == si) v[j] = -CUDART_INF_F;
        __syncthreads();
    }

    for (int c = tid; c < CC; c += 256) {
        const float* xb = x + ((size_t)(b * CC + c)) * NN;
        float m = -CUDART_INF_F;
        #pragma unroll
        for (int j = 0; j < 8; j++) m = fmaxf(m, xb[sel[j]]);
        g_mp[b * CC + c] = m;
    }
}

// ---------------------------------------------------------------------------
// Kernel 5: out = x + max_pooled broadcast
// ---------------------------------------------------------------------------
__global__ void add_kernel(const float* __restrict__ x, float* __restrict__ out) {
    int i = blockIdx.x * 256 + threadIdx.x;
    int bc = i >> 10;
    out[i] = x[i] + g_mp[bc];
}

// ---------------------------------------------------------------------------
extern "C" void kernel_launch(void* const* d_in, const int* in_sizes, int n_in,
                              void* d_out, int out_size) {
    const float* x    = (const float*)d_in[0];
    const float* W    = (const float*)d_in[1];
    const float* bias = (const float*)d_in[2];
    float* out = (float*)d_out;

    cudaFuncSetAttribute(attn_kernel, cudaFuncAttributeMaxDynamicSharedMemorySize, SMEM2);

    proj_kernel<<<dim3(16, 128), 256>>>(x, W, bias);
    attn_kernel<<<256, 256, SMEM2>>>();
    zero_ks_kernel<<<8, 1024>>>();
    colsum_kernel<<<128, 256>>>();
    topk_kernel<<<8, 256>>>(x);
    add_kernel<<<(BB * CC * NN) / 256, 256>>>(x, out);
}

// round 6
// speedup vs baseline: 1.3111x; 1.3111x over previous
#include <cuda_runtime.h>
#include <math_constants.h>

#define BB 8
#define CC 512
#define NN 1024
#define HH 8
#define DD 64

// Scratch (allocation-free: __device__ globals)
__device__ float  g_q[BB*HH*NN*DD];     // 16 MB: Q[b][h][n][d]
__device__ float  g_k[BB*HH*NN*DD];     // 16 MB: K[b][h][n][d]
__device__ float  g_attn[BB*NN*NN];     // 32 MB: sum over heads of softmax rows
__device__ double g_rinv[BB*NN];        // 1 / row-sum of exp(attn/256)
__device__ double g_ksc[BB*NN];         // key_scores accumulators (fp64)
__device__ float  g_mp[BB*CC];          // max-pooled (B, C)

// exp(x) for x in [0, 1/32], fp32 degree-4 Taylor.
// Truncation x^5/120 <= 2.6e-10; rounding ~2 ulp (~1.2e-7 rel). Per-term errors
// average down ~32-1000x in the row/column means -- far under the ~6e-7 rel
// half-gap at the top-k rank boundary. Accumulations stay fp64.
__device__ __forceinline__ float exp_small_f(float x) {
    float p = 1.f / 24.f;
    p = fmaf(p, x, 1.f / 6.f);
    p = fmaf(p, x, 0.5f);
    p = fmaf(p, x, 1.f);
    p = fmaf(p, x, 1.f);
    return p;
}

// ---------------------------------------------------------------------------
// Kernel 1: fused Q/K projection.
// ---------------------------------------------------------------------------
__global__ __launch_bounds__(256) void proj_kernel(const float* __restrict__ x,
                                                   const float* __restrict__ W,
                                                   const float* __restrict__ bias) {
    __shared__ float As[16][65];
    __shared__ float Bs[16][65];
    int tid = threadIdx.x;
    int tx = tid & 15, ty = tid >> 4;
    int j0 = blockIdx.x * 64;
    int m0 = blockIdx.y * 64;
    int b  = m0 >> 10;
    int n0 = m0 & 1023;
    const float* xb = x + (size_t)b * CC * NN;

    float acc[4][4];
    #pragma unroll
    for (int i = 0; i < 4; i++)
        #pragma unroll
        for (int j = 0; j < 4; j++) acc[i][j] = 0.f;

    for (int kb = 0; kb < CC; kb += 16) {
        #pragma unroll
        for (int p = 0; p < 4; p++) {
            int e = tid + p * 256;
            int kk = e >> 6, m = e & 63;
            As[kk][m] = xb[(kb + kk) * NN + n0 + m];
        }
        #pragma unroll
        for (int p = 0; p < 4; p++) {
            int e = tid + p * 256;
            int kk = e & 15, jl = e >> 4;
            Bs[kk][jl] = W[(size_t)(j0 + jl) * CC + kb + kk];
        }
        __syncthreads();
        #pragma unroll
        for (int kk = 0; kk < 16; kk++) {
            float a[4], bv[4];
            #pragma unroll
            for (int i = 0; i < 4; i++) a[i] = As[kk][ty * 4 + i];
            #pragma unroll
            for (int j = 0; j < 4; j++) bv[j] = Bs[kk][tx + j * 16];
            #pragma unroll
            for (int i = 0; i < 4; i++)
                #pragma unroll
                for (int j = 0; j < 4; j++) acc[i][j] += a[i] * bv[j];
        }
        __syncthreads();
    }

    #pragma unroll
    for (int j = 0; j < 4; j++) {
        int jg = j0 + tx + j * 16;
        float bsv = bias[jg];
        int head = (jg & 511) >> 6;
        int dd   = jg & 63;
        float* dst = (jg < 512) ? g_q : g_k;
        #pragma unroll
        for (int i = 0; i < 4; i++) {
            int n = n0 + ty * 4 + i;
            dst[((size_t)(b * HH + head) * NN + n) * DD + dd] = acc[i][j] + bsv;
        }
    }
}

// ---------------------------------------------------------------------------
// Kernel 2: scores + per-head softmax + head accumulation. (No w2 fusion --
// the serial DFMA chain on this kernel's critical path cost 165us in R5.)
// ---------------------------------------------------------------------------
#define SMEM2 ((2080 + 8320 + 32 * 1024) * 4)

__global__ __launch_bounds__(256) void attn_kernel() {
    extern __shared__ float sm[];
    float* Qs = sm;               // [32][65]
    float* Ks = sm + 2080;        // [128][65]
    float* S  = sm + 2080 + 8320; // [32][1024]

    int tid = threadIdx.x;
    int b  = blockIdx.x >> 5;
    int q0 = (blockIdx.x & 31) << 5;
    int tx = tid & 31, ty = tid >> 5;

    for (int h = 0; h < HH; h++) {
        const float* Qg = g_q + ((size_t)(b * HH + h) * NN + q0) * DD;
        const float* Kg = g_k + (size_t)(b * HH + h) * NN * DD;

        #pragma unroll
        for (int p = 0; p < 8; p++) {
            int e = tid + p * 256;
            int r = e >> 6, dd = e & 63;
            Qs[r * 65 + dd] = Qg[r * DD + dd];
        }

        for (int kt = 0; kt < 8; kt++) {
            int k0 = kt * 128;
            __syncthreads();
            #pragma unroll
            for (int p = 0; p < 32; p++) {
                int e = tid + p * 256;
                int r = e >> 6, dd = e & 63;
                Ks[r * 65 + dd] = Kg[(k0 + r) * DD + dd];
            }
            __syncthreads();

            float acc[4][4] = {};
            #pragma unroll
            for (int kk = 0; kk < 64; kk++) {
                float a[4], bv[4];
                #pragma unroll
                for (int i = 0; i < 4; i++) a[i] = Qs[(ty * 4 + i) * 65 + kk];
                #pragma unroll
                for (int j = 0; j < 4; j++) bv[j] = Ks[(tx + j * 32) * 65 + kk];
                #pragma unroll
                for (int i = 0; i < 4; i++)
                    #pragma unroll
                    for (int j = 0; j < 4; j++) acc[i][j] += a[i] * bv[j];
            }
            #pragma unroll
            for (int i = 0; i < 4; i++)
                #pragma unroll
                for (int j = 0; j < 4; j++)
                    S[(ty * 4 + i) * 1024 + k0 + tx + j * 32] = acc[i][j] * 0.125f;
        }
        __syncthreads();

        #pragma unroll
        for (int r = 0; r < 4; r++) {
            int row = ty * 4 + r;
            float* Sr = S + row * 1024;
            float m = -CUDART_INF_F;
            for (int c = tx; c < 1024; c += 32) m = fmaxf(m, Sr[c]);
            #pragma unroll
            for (int o = 16; o; o >>= 1) m = fmaxf(m, __shfl_xor_sync(~0u, m, o));
            float s = 0.f;
            for (int c = tx; c < 1024; c += 32) { float e = expf(Sr[c] - m); Sr[c] = e; s += e; }
            #pragma unroll
            for (int o = 16; o; o >>= 1) s += __shfl_xor_sync(~0u, s, o);
            float inv = 1.f / s;
            float* gp = g_attn + ((size_t)(b * NN + q0 + row)) * NN;
            if (h == 0) { for (int c = tx; c < 1024; c += 32) gp[c]  = Sr[c] * inv; }
            else        { for (int c = tx; c < 1024; c += 32) gp[c] += Sr[c] * inv; }
        }
        __syncthreads();
    }
}

// ---------------------------------------------------------------------------
// Kernel 3a: w2 row sums. One row per warp, barrier-free, fp32 poly + fp64 acc
// with 2 independent chains. grid=1024 blocks (7/SM).
// ---------------------------------------------------------------------------
__global__ __launch_bounds__(256) void rowsum_kernel() {
    int row  = blockIdx.x * 8 + (threadIdx.x >> 5);   // [0, 8192)
    int lane = threadIdx.x & 31;
    const float* gp = g_attn + (size_t)row * NN;

    double s0 = 0.0, s1 = 0.0;
    #pragma unroll
    for (int c = 0; c < NN; c += 64) {
        float v0 = gp[c + lane];
        float v1 = gp[c + lane + 32];
        s0 += (double)exp_small_f(v0 * (1.f / 256.f));
        s1 += (double)exp_small_f(v1 * (1.f / 256.f));
    }
    double s = s0 + s1;
    #pragma unroll
    for (int o = 16; o; o >>= 1) s += __shfl_xor_sync(~0u, s, o);
    if (lane == 0) g_rinv[row] = 1.0 / s;
}

// ---------------------------------------------------------------------------
// Kernel 3b: column accumulation. 16-row chunks (grid=512), 4 cols/thread,
// fp32 poly + one fp64 fma per element, fp64 atomicAdd at the end.
// ---------------------------------------------------------------------------
__global__ void zero_ks_kernel() {
    g_ksc[blockIdx.x * 1024 + threadIdx.x] = 0.0;
}

__global__ __launch_bounds__(256) void colsum_kernel() {
    int b  = blockIdx.x >> 6;
    int q0 = (blockIdx.x & 63) << 4;
    int tid = threadIdx.x;
    const float* base = g_attn + ((size_t)b * NN + q0) * NN;
    const double* rinv = g_rinv + b * NN + q0;

    double acc[4] = {0.0, 0.0, 0.0, 0.0};
    #pragma unroll 4
    for (int q = 0; q < 16; q++) {
        const float* row = base + (size_t)q * NN;
        double inv = rinv[q];
        float e[4];
        #pragma unroll
        for (int j = 0; j < 4; j++) e[j] = exp_small_f(row[tid + j * 256] * (1.f / 256.f));
        #pragma unroll
        for (int j = 0; j < 4; j++) acc[j] = fma((double)e[j], inv, acc[j]);
    }
    #pragma unroll
    for (int j = 0; j < 4; j++)
        atomicAdd(&g_ksc[b * NN + tid + j * 256], acc[j] * (1.0 / 1024.0));
}

// ---------------------------------------------------------------------------
// Kernel 4: top-8 per batch, FP32 compares (matches reference's fp32
// quantization of key_scores; ties broken by lower index), then max-pool.
// ---------------------------------------------------------------------------
__global__ __launch_bounds__(256) void topk_kernel(const float* __restrict__ x) {
    __shared__ float bvv[8];
    __shared__ int   bii[8];
    __shared__ int   sel[8];
    __shared__ int   sbi;
    int b = blockIdx.x;
    int tid = threadIdx.x;
    int lane = tid & 31, warp = tid >> 5;

    float v[4]; int idx[4];
    #pragma unroll
    for (int j = 0; j < 4; j++) {
        idx[j] = tid + j * 256;
        v[j] = (float)g_ksc[b * NN + idx[j]];   // round-to-nearest fp32, like ref
    }

    for (int it = 0; it < 8; it++) {
        float mv = v[0]; int mi = idx[0];
        #pragma unroll
        for (int j = 1; j < 4; j++)
            if (v[j] > mv || (v[j] == mv && idx[j] < mi)) { mv = v[j]; mi = idx[j]; }
        #pragma unroll
        for (int o = 16; o; o >>= 1) {
            float ov = __shfl_xor_sync(~0u, mv, o);
            int   oi = __shfl_xor_sync(~0u, mi, o);
            if (ov > mv || (ov == mv && oi < mi)) { mv = ov; mi = oi; }
        }
        if (lane == 0) { bvv[warp] = mv; bii[warp] = mi; }
        __syncthreads();
        if (tid == 0) {
            float m2 = bvv[0]; int i2 = bii[0];
            for (int w = 1; w < 8; w++)
                if (bvv[w] > m2 || (bvv[w] == m2 && bii[w] < i2)) { m2 = bvv[w]; i2 = bii[w]; }
            sel[it] = i2; sbi = i2;
        }
        __syncthreads();
        int si = sbi;
        #pragma unroll
        for (int j = 0; j < 4; j++) if (idx[j] == si) v[j] = -CUDART_INF_F;
        __syncthreads();
    }

    for (int c = tid; c < CC; c += 256) {
        const float* xb = x + ((size_t)(b * CC + c)) * NN;
        float m = -CUDART_INF_F;
        #pragma unroll
        for (int j = 0; j < 8; j++) m = fmaxf(m, xb[sel[j]]);
        g_mp[b * CC + c] = m;
    }
}

// ---------------------------------------------------------------------------
// Kernel 5: out = x + max_pooled broadcast
// ---------------------------------------------------------------------------
__global__ void add_kernel(const float* __restrict__ x, float* __restrict__ out) {
    int i = blockIdx.x * 256 + threadIdx.x;
    int bc = i >> 10;
    out[i] = x[i] + g_mp[bc];
}

// ---------------------------------------------------------------------------
extern "C" void kernel_launch(void* const* d_in, const int* in_sizes, int n_in,
                              void* d_out, int out_size) {
    const float* x    = (const float*)d_in[0];
    const float* W    = (const float*)d_in[1];
    const float* bias = (const float*)d_in[2];
    float* out = (float*)d_out;

    cudaFuncSetAttribute(attn_kernel, cudaFuncAttributeMaxDynamicSharedMemorySize, SMEM2);

    proj_kernel<<<dim3(16, 128), 256>>>(x, W, bias);
    attn_kernel<<<256, 256, SMEM2>>>();
    rowsum_kernel<<<1024, 256>>>();
    zero_ks_kernel<<<8, 1024>>>();
    colsum_kernel<<<512, 256>>>();
    topk_kernel<<<8, 256>>>(x);
    add_kernel<<<(BB * CC * NN) / 256, 256>>>(x, out);
}

// round 7
// speedup vs baseline: 1.4082x; 1.0740x over previous
#include <cuda_runtime.h>
#include <math_constants.h>

#define BB 8
#define CC 512
#define NN 1024
#define HH 8
#define DD 64

// Scratch (allocation-free: __device__ globals)
__device__ float  g_q[BB*HH*NN*DD];     // 16 MB: Q[b][h][n][d]
__device__ float  g_k[BB*HH*NN*DD];     // 16 MB: K[b][h][n][d]
__device__ float  g_attn[BB*NN*NN];     // 32 MB: sum over heads of softmax rows
__device__ double g_rinv[BB*NN];        // 1 / row-sum of exp(attn/256)
__device__ double g_ksc[BB*NN];         // key_scores accumulators (fp64)
__device__ float  g_mp[BB*CC];          // max-pooled (B, C)

// ---- packed f32x2 helpers (FFMA2: 2x fp32 FMA throughput on sm_103a) ------
__device__ __forceinline__ unsigned long long f2pack(float lo, float hi) {
    unsigned long long r;
    asm("mov.b64 %0, {%1, %2};" : "=l"(r) : "f"(lo), "f"(hi));
    return r;
}
__device__ __forceinline__ unsigned long long ffma2(unsigned long long a,
                                                    unsigned long long b,
                                                    unsigned long long c) {
    unsigned long long d;
    asm("fma.rn.f32x2 %0, %1, %2, %3;" : "=l"(d) : "l"(a), "l"(b), "l"(c));
    return d;
}
__device__ __forceinline__ float2 f2unpack(unsigned long long v) {
    float lo, hi;
    asm("mov.b64 {%0, %1}, %2;" : "=f"(lo), "=f"(hi) : "l"(v));
    return make_float2(lo, hi);
}

// exp(x) for x in [0, 1/32], fp32 degree-4 Taylor (see round-6 error budget).
__device__ __forceinline__ float exp_small_f(float x) {
    float p = 1.f / 24.f;
    p = fmaf(p, x, 1.f / 6.f);
    p = fmaf(p, x, 0.5f);
    p = fmaf(p, x, 1.f);
    p = fmaf(p, x, 1.f);
    return p;
}

// ---------------------------------------------------------------------------
// Kernel 1: fused Q/K projection, FFMA2 microkernel.
// 64x64 tile, 256 threads; thread (tx,ty) owns j-cols {2tx,2tx+1,32+2tx,32+2tx+1}
// and m-rows ty*4..+3. Per kk: a = LDS.128 broadcast, b = 2x LDS.64.
// ---------------------------------------------------------------------------
__global__ __launch_bounds__(256) void proj_kernel(const float* __restrict__ x,
                                                   const float* __restrict__ W,
                                                   const float* __restrict__ bias) {
    __shared__ float As[16][68];   // stride%4==0 for float4 loads
    __shared__ float Bs[16][66];   // stride even for float2 loads
    int tid = threadIdx.x;
    int tx = tid & 15, ty = tid >> 4;
    int j0 = blockIdx.x * 64;
    int m0 = blockIdx.y * 64;
    int b  = m0 >> 10;
    int n0 = m0 & 1023;
    const float* xb = x + (size_t)b * CC * NN;

    unsigned long long acc[4][2];
    #pragma unroll
    for (int i = 0; i < 4; i++) { acc[i][0] = 0ull; acc[i][1] = 0ull; }

    for (int kb = 0; kb < CC; kb += 16) {
        #pragma unroll
        for (int p = 0; p < 4; p++) {
            int e = tid + p * 256;
            int kk = e >> 6, m = e & 63;
            As[kk][m] = xb[(kb + kk) * NN + n0 + m];
        }
        #pragma unroll
        for (int p = 0; p < 4; p++) {
            int e = tid + p * 256;
            int kk = e & 15, jl = e >> 4;
            Bs[kk][jl] = W[(size_t)(j0 + jl) * CC + kb + kk];
        }
        __syncthreads();
        #pragma unroll
        for (int kk = 0; kk < 16; kk++) {
            float4 aq = *(const float4*)&As[kk][ty * 4];
            float2 b0 = *(const float2*)&Bs[kk][2 * tx];
            float2 b1 = *(const float2*)&Bs[kk][32 + 2 * tx];
            unsigned long long B0 = f2pack(b0.x, b0.y);
            unsigned long long B1 = f2pack(b1.x, b1.y);
            float av[4] = {aq.x, aq.y, aq.z, aq.w};
            #pragma unroll
            for (int i = 0; i < 4; i++) {
                unsigned long long A = f2pack(av[i], av[i]);
                acc[i][0] = ffma2(A, B0, acc[i][0]);
                acc[i][1] = ffma2(A, B1, acc[i][1]);
            }
        }
        __syncthreads();
    }

    // Epilogue: j0%64==0 so dd = jl; adjacent col pairs -> coalesced float2.
    float2 bs0 = *(const float2*)&bias[j0 + 2 * tx];
    float2 bs1 = *(const float2*)&bias[j0 + 32 + 2 * tx];
    #pragma unroll
    for (int p = 0; p < 2; p++) {
        int jl = p * 32 + 2 * tx;
        int jg = j0 + jl;
        int head = (jg & 511) >> 6;
        float2 bsv = p ? bs1 : bs0;
        float* dst = ((jg < 512) ? g_q : g_k) + (size_t)(b * HH + head) * NN * DD;
        #pragma unroll
        for (int i = 0; i < 4; i++) {
            int n = n0 + ty * 4 + i;
            float2 u = f2unpack(acc[i][p]);
            *(float2*)&dst[(size_t)n * DD + jl] = make_float2(u.x + bsv.x, u.y + bsv.y);
        }
    }
}

// ---------------------------------------------------------------------------
// Kernel 2: scores + per-head softmax + head accumulation, FFMA2 microkernel.
// Block = (b, 32 q rows). K stored d-major (transposed) in smem; k-tile 256,
// microtile 4q x 8k. Per kk: a = LDS.128 broadcast, b = 2x LDS.128.
// smem: Qs_t[64][36] + Ks_t[64][260] + S[32][1024] = 206848 B.
// ---------------------------------------------------------------------------
#define QS_STRIDE 36
#define KS_STRIDE 260
#define SMEM2 ((64*QS_STRIDE + 64*KS_STRIDE + 32*1024) * 4)

__global__ __launch_bounds__(256) void attn_kernel() {
    extern __shared__ float sm[];
    float* Qs = sm;                             // [64][36]  (d-major: [dd][q])
    float* Ks = sm + 64 * QS_STRIDE;            // [64][260] (d-major: [dd][k])
    float* S  = sm + 64 * (QS_STRIDE + KS_STRIDE); // [32][1024]

    int tid = threadIdx.x;
    int b  = blockIdx.x >> 5;
    int q0 = (blockIdx.x & 31) << 5;
    int tx = tid & 31, ty = tid >> 5;

    for (int h = 0; h < HH; h++) {
        const float* Qg = g_q + ((size_t)(b * HH + h) * NN + q0) * DD;
        const float* Kg = g_k + (size_t)(b * HH + h) * NN * DD;

        __syncthreads();   // prev softmax done before overwriting Qs
        #pragma unroll
        for (int p = 0; p < 8; p++) {           // Qs_t: 32 q x 64 d, transposed
            int e = tid + p * 256;
            int dd = e & 63, r = e >> 6;
            Qs[dd * QS_STRIDE + r] = Qg[r * DD + dd];
        }

        for (int kt = 0; kt < 4; kt++) {
            int k0 = kt * 256;
            __syncthreads();                    // prev compute done / Qs visible
            #pragma unroll
            for (int p = 0; p < 64; p++) {      // Ks_t: 256 k x 64 d, transposed
                int e = tid + p * 256;
                int dd = e & 63, r = e >> 6;
                Ks[dd * KS_STRIDE + r] = Kg[(size_t)(k0 + r) * DD + dd];
            }
            __syncthreads();

            unsigned long long acc[4][4];
            #pragma unroll
            for (int i = 0; i < 4; i++)
                #pragma unroll
                for (int j = 0; j < 4; j++) acc[i][j] = 0ull;

            #pragma unroll 4
            for (int kk = 0; kk < 64; kk++) {
                float4 aq = *(const float4*)&Qs[kk * QS_STRIDE + ty * 4];
                float4 b0 = *(const float4*)&Ks[kk * KS_STRIDE + 4 * tx];
                float4 b1 = *(const float4*)&Ks[kk * KS_STRIDE + 128 + 4 * tx];
                unsigned long long B00 = f2pack(b0.x, b0.y);
                unsigned long long B01 = f2pack(b0.z, b0.w);
                unsigned long long B10 = f2pack(b1.x, b1.y);
                unsigned long long B11 = f2pack(b1.z, b1.w);
                float av[4] = {aq.x, aq.y, aq.z, aq.w};
                #pragma unroll
                for (int i = 0; i < 4; i++) {
                    unsigned long long A = f2pack(av[i], av[i]);
                    acc[i][0] = ffma2(A, B00, acc[i][0]);
                    acc[i][1] = ffma2(A, B01, acc[i][1]);
                    acc[i][2] = ffma2(A, B10, acc[i][2]);
                    acc[i][3] = ffma2(A, B11, acc[i][3]);
                }
            }
            #pragma unroll
            for (int i = 0; i < 4; i++) {
                int row = ty * 4 + i;
                float2 u0 = f2unpack(acc[i][0]);
                float2 u1 = f2unpack(acc[i][1]);
                float2 u2 = f2unpack(acc[i][2]);
                float2 u3 = f2unpack(acc[i][3]);
                *(float4*)&S[row * 1024 + k0 + 4 * tx] =
                    make_float4(u0.x * 0.125f, u0.y * 0.125f, u1.x * 0.125f, u1.y * 0.125f);
                *(float4*)&S[row * 1024 + k0 + 128 + 4 * tx] =
                    make_float4(u2.x * 0.125f, u2.y * 0.125f, u3.x * 0.125f, u3.y * 0.125f);
            }
        }
        __syncthreads();

        #pragma unroll
        for (int r = 0; r < 4; r++) {
            int row = ty * 4 + r;
            float* Sr = S + row * 1024;
            float m = -CUDART_INF_F;
            for (int c = tx; c < 1024; c += 32) m = fmaxf(m, Sr[c]);
            #pragma unroll
            for (int o = 16; o; o >>= 1) m = fmaxf(m, __shfl_xor_sync(~0u, m, o));
            float s = 0.f;
            for (int c = tx; c < 1024; c += 32) { float e = expf(Sr[c] - m); Sr[c] = e; s += e; }
            #pragma unroll
            for (int o = 16; o; o >>= 1) s += __shfl_xor_sync(~0u, s, o);
            float inv = 1.f / s;
            float* gp = g_attn + ((size_t)(b * NN + q0 + row)) * NN;
            if (h == 0) { for (int c = tx; c < 1024; c += 32) gp[c]  = Sr[c] * inv; }
            else        { for (int c = tx; c < 1024; c += 32) gp[c] += Sr[c] * inv; }
        }
    }
}

// ---------------------------------------------------------------------------
// Kernel 3a: w2 row sums. One row per warp, barrier-free.
// ---------------------------------------------------------------------------
__global__ __launch_bounds__(256) void rowsum_kernel() {
    int row  = blockIdx.x * 8 + (threadIdx.x >> 5);
    int lane = threadIdx.x & 31;
    const float* gp = g_attn + (size_t)row * NN;

    double s0 = 0.0, s1 = 0.0;
    #pragma unroll
    for (int c = 0; c < NN; c += 64) {
        float v0 = gp[c + lane];
        float v1 = gp[c + lane + 32];
        s0 += (double)exp_small_f(v0 * (1.f / 256.f));
        s1 += (double)exp_small_f(v1 * (1.f / 256.f));
    }
    double s = s0 + s1;
    #pragma unroll
    for (int o = 16; o; o >>= 1) s += __shfl_xor_sync(~0u, s, o);
    if (lane == 0) g_rinv[row] = 1.0 / s;
}

// ---------------------------------------------------------------------------
// Kernel 3b: column accumulation.
// ---------------------------------------------------------------------------
__global__ void zero_ks_kernel() {
    g_ksc[blockIdx.x * 1024 + threadIdx.x] = 0.0;
}

__global__ __launch_bounds__(256) void colsum_kernel() {
    int b  = blockIdx.x >> 6;
    int q0 = (blockIdx.x & 63) << 4;
    int tid = threadIdx.x;
    const float* base = g_attn + ((size_t)b * NN + q0) * NN;
    const double* rinv = g_rinv + b * NN + q0;

    double acc[4] = {0.0, 0.0, 0.0, 0.0};
    #pragma unroll 4
    for (int q = 0; q < 16; q++) {
        const float* row = base + (size_t)q * NN;
        double inv = rinv[q];
        float e[4];
        #pragma unroll
        for (int j = 0; j < 4; j++) e[j] = exp_small_f(row[tid + j * 256] * (1.f / 256.f));
        #pragma unroll
        for (int j = 0; j < 4; j++) acc[j] = fma((double)e[j], inv, acc[j]);
    }
    #pragma unroll
    for (int j = 0; j < 4; j++)
        atomicAdd(&g_ksc[b * NN + tid + j * 256], acc[j] * (1.0 / 1024.0));
}

// ---------------------------------------------------------------------------
// Kernel 4: top-8 per batch, fp32-quantized compares + lowest-index ties.
// ---------------------------------------------------------------------------
__global__ __launch_bounds__(256) void topk_kernel(const float* __restrict__ x) {
    __shared__ float bvv[8];
    __shared__ int   bii[8];
    __shared__ int   sel[8];
    __shared__ int   sbi;
    int b = blockIdx.x;
    int tid = threadIdx.x;
    int lane = tid & 31, warp = tid >> 5;

    float v[4]; int idx[4];
    #pragma unroll
    for (int j = 0; j < 4; j++) {
        idx[j] = tid + j * 256;
        v[j] = (float)g_ksc[b * NN + idx[j]];
    }

    for (int it = 0; it < 8; it++) {
        float mv = v[0]; int mi = idx[0];
        #pragma unroll
        for (int j = 1; j < 4; j++)
            if (v[j] > mv || (v[j] == mv && idx[j] < mi)) { mv = v[j]; mi = idx[j]; }
        #pragma unroll
        for (int o = 16; o; o >>= 1) {
            float ov = __shfl_xor_sync(~0u, mv, o);
            int   oi = __shfl_xor_sync(~0u, mi, o);
            if (ov > mv || (ov == mv && oi < mi)) { mv = ov; mi = oi; }
        }
        if (lane == 0) { bvv[warp] = mv; bii[warp] = mi; }
        __syncthreads();
        if (tid == 0) {
            float m2 = bvv[0]; int i2 = bii[0];
            for (int w = 1; w < 8; w++)
                if (bvv[w] > m2 || (bvv[w] == m2 && bii[w] < i2)) { m2 = bvv[w]; i2 = bii[w]; }
            sel[it] = i2; sbi = i2;
        }
        __syncthreads();
        int si = sbi;
        #pragma unroll
        for (int j = 0; j < 4; j++) if (idx[j] == si) v[j] = -CUDART_INF_F;
        __syncthreads();
    }

    for (int c = tid; c < CC; c += 256) {
        const float* xb = x + ((size_t)(b * CC + c)) * NN;
        float m = -CUDART_INF_F;
        #pragma unroll
        for (int j = 0; j < 8; j++) m = fmaxf(m, xb[sel[j]]);
        g_mp[b * CC + c] = m;
    }
}

// ---------------------------------------------------------------------------
// Kernel 5: out = x + max_pooled broadcast
// ---------------------------------------------------------------------------
__global__ void add_kernel(const float* __restrict__ x, float* __restrict__ out) {
    int i = blockIdx.x * 256 + threadIdx.x;
    int bc = i >> 10;
    out[i] = x[i] + g_mp[bc];
}

// ---------------------------------------------------------------------------
extern "C" void kernel_launch(void* const* d_in, const int* in_sizes, int n_in,
                              void* d_out, int out_size) {
    const float* x    = (const float*)d_in[0];
    const float* W    = (const float*)d_in[1];
    const float* bias = (const float*)d_in[2];
    float* out = (float*)d_out;

    cudaFuncSetAttribute(attn_kernel, cudaFuncAttributeMaxDynamicSharedMemorySize, SMEM2);

    proj_kernel<<<dim3(16, 128), 256>>>(x, W, bias);
    attn_kernel<<<256, 256, SMEM2>>>();
    rowsum_kernel<<<1024, 256>>>();
    zero_ks_kernel<<<8, 1024>>>();
    colsum_kernel<<<512, 256>>>();
    topk_kernel<<<8, 256>>>(x);
    add_kernel<<<(BB * CC * NN) / 256, 256>>>(x, out);
}

// round 8
// speedup vs baseline: 1.6055x; 1.1401x over previous
#include <cuda_runtime.h>
#include <math_constants.h>

#define BB 8
#define CC 512
#define NN 1024
#define HH 8
#define DD 64

// Scratch (allocation-free: __device__ globals)
__device__ float  g_q[BB*HH*NN*DD];     // 16 MB: Q[b][h][n][d]
__device__ float  g_k[BB*HH*NN*DD];     // 16 MB: K[b][h][n][d]
__device__ float  g_attn[BB*NN*NN];     // 32 MB: sum over heads of softmax rows
__device__ double g_rinv[BB*NN];        // 1 / row-sum of exp(attn/256)
__device__ double g_ksc[BB*NN];         // key_scores accumulators (fp64)
__device__ float  g_mp[BB*CC];          // max-pooled (B, C)

// ---- packed f32x2 helpers (FFMA2: 2x fp32 FMA throughput on sm_103a) ------
__device__ __forceinline__ unsigned long long f2pack(float lo, float hi) {
    unsigned long long r;
    asm("mov.b64 %0, {%1, %2};" : "=l"(r) : "f"(lo), "f"(hi));
    return r;
}
__device__ __forceinline__ unsigned long long ffma2(unsigned long long a,
                                                    unsigned long long b,
                                                    unsigned long long c) {
    unsigned long long d;
    asm("fma.rn.f32x2 %0, %1, %2, %3;" : "=l"(d) : "l"(a), "l"(b), "l"(c));
    return d;
}
__device__ __forceinline__ float2 f2unpack(unsigned long long v) {
    float lo, hi;
    asm("mov.b64 {%0, %1}, %2;" : "=f"(lo), "=f"(hi) : "l"(v));
    return make_float2(lo, hi);
}

// exp(x) for x in [0, 1/32], fp32 degree-4 Taylor (see round-6 error budget).
__device__ __forceinline__ float exp_small_f(float x) {
    float p = 1.f / 24.f;
    p = fmaf(p, x, 1.f / 6.f);
    p = fmaf(p, x, 0.5f);
    p = fmaf(p, x, 1.f);
    p = fmaf(p, x, 1.f);
    return p;
}

// ---------------------------------------------------------------------------
// Kernel 1: fused Q/K projection, FFMA2 microkernel.
// ---------------------------------------------------------------------------
__global__ __launch_bounds__(256) void proj_kernel(const float* __restrict__ x,
                                                   const float* __restrict__ W,
                                                   const float* __restrict__ bias) {
    __shared__ float As[16][68];
    __shared__ float Bs[16][66];
    int tid = threadIdx.x;
    int tx = tid & 15, ty = tid >> 4;
    int j0 = blockIdx.x * 64;
    int m0 = blockIdx.y * 64;
    int b  = m0 >> 10;
    int n0 = m0 & 1023;
    const float* xb = x + (size_t)b * CC * NN;

    unsigned long long acc[4][2];
    #pragma unroll
    for (int i = 0; i < 4; i++) { acc[i][0] = 0ull; acc[i][1] = 0ull; }

    for (int kb = 0; kb < CC; kb += 16) {
        #pragma unroll
        for (int p = 0; p < 4; p++) {
            int e = tid + p * 256;
            int kk = e >> 6, m = e & 63;
            As[kk][m] = xb[(kb + kk) * NN + n0 + m];
        }
        #pragma unroll
        for (int p = 0; p < 4; p++) {
            int e = tid + p * 256;
            int kk = e & 15, jl = e >> 4;
            Bs[kk][jl] = W[(size_t)(j0 + jl) * CC + kb + kk];
        }
        __syncthreads();
        #pragma unroll
        for (int kk = 0; kk < 16; kk++) {
            float4 aq = *(const float4*)&As[kk][ty * 4];
            float2 b0 = *(const float2*)&Bs[kk][2 * tx];
            float2 b1 = *(const float2*)&Bs[kk][32 + 2 * tx];
            unsigned long long B0 = f2pack(b0.x, b0.y);
            unsigned long long B1 = f2pack(b1.x, b1.y);
            float av[4] = {aq.x, aq.y, aq.z, aq.w};
            #pragma unroll
            for (int i = 0; i < 4; i++) {
                unsigned long long A = f2pack(av[i], av[i]);
                acc[i][0] = ffma2(A, B0, acc[i][0]);
                acc[i][1] = ffma2(A, B1, acc[i][1]);
            }
        }
        __syncthreads();
    }

    float2 bs0 = *(const float2*)&bias[j0 + 2 * tx];
    float2 bs1 = *(const float2*)&bias[j0 + 32 + 2 * tx];
    #pragma unroll
    for (int p = 0; p < 2; p++) {
        int jl = p * 32 + 2 * tx;
        int jg = j0 + jl;
        int head = (jg & 511) >> 6;
        float2 bsv = p ? bs1 : bs0;
        float* dst = ((jg < 512) ? g_q : g_k) + (size_t)(b * HH + head) * NN * DD;
        #pragma unroll
        for (int i = 0; i < 4; i++) {
            int n = n0 + ty * 4 + i;
            float2 u = f2unpack(acc[i][p]);
            *(float2*)&dst[(size_t)n * DD + jl] = make_float2(u.x + bsv.x, u.y + bsv.y);
        }
    }
}

// ---------------------------------------------------------------------------
// Kernel 2: scores + per-head softmax + head accumulation.
// Max-free softmax (logits bounded, exp can't overflow; softmax shift-
// invariant): exp fused into GEMM epilogue via __expf on register values,
// row-sum partials kept in registers, one shuffle reduce, then a single
// float4 scale+accumulate pass. smem: Qs_t[64][36]+Ks_t[64][260]+S[32][1024].
// ---------------------------------------------------------------------------
#define QS_STRIDE 36
#define KS_STRIDE 260
#define SMEM2 ((64*QS_STRIDE + 64*KS_STRIDE + 32*1024) * 4)

__global__ __launch_bounds__(256) void attn_kernel() {
    extern __shared__ float sm[];
    float* Qs = sm;                                // [64][36]  d-major
    float* Ks = sm + 64 * QS_STRIDE;               // [64][260] d-major
    float* S  = sm + 64 * (QS_STRIDE + KS_STRIDE); // [32][1024] exp'd scores

    int tid = threadIdx.x;
    int b  = blockIdx.x >> 5;
    int q0 = (blockIdx.x & 31) << 5;
    int tx = tid & 31, ty = tid >> 5;

    for (int h = 0; h < HH; h++) {
        const float* Qg = g_q + ((size_t)(b * HH + h) * NN + q0) * DD;
        const float* Kg = g_k + (size_t)(b * HH + h) * NN * DD;

        __syncthreads();   // prev head's S-consume done before overwriting Qs/S
        #pragma unroll
        for (int p = 0; p < 8; p++) {
            int e = tid + p * 256;
            int dd = e & 63, r = e >> 6;
            Qs[dd * QS_STRIDE + r] = Qg[r * DD + dd];
        }

        float rowpart[4] = {0.f, 0.f, 0.f, 0.f};

        for (int kt = 0; kt < 4; kt++) {
            int k0 = kt * 256;
            __syncthreads();
            #pragma unroll
            for (int p = 0; p < 64; p++) {
                int e = tid + p * 256;
                int dd = e & 63, r = e >> 6;
                Ks[dd * KS_STRIDE + r] = Kg[(size_t)(k0 + r) * DD + dd];
            }
            __syncthreads();

            unsigned long long acc[4][4];
            #pragma unroll
            for (int i = 0; i < 4; i++)
                #pragma unroll
                for (int j = 0; j < 4; j++) acc[i][j] = 0ull;

            #pragma unroll 4
            for (int kk = 0; kk < 64; kk++) {
                float4 aq = *(const float4*)&Qs[kk * QS_STRIDE + ty * 4];
                float4 b0 = *(const float4*)&Ks[kk * KS_STRIDE + 4 * tx];
                float4 b1 = *(const float4*)&Ks[kk * KS_STRIDE + 128 + 4 * tx];
                unsigned long long B00 = f2pack(b0.x, b0.y);
                unsigned long long B01 = f2pack(b0.z, b0.w);
                unsigned long long B10 = f2pack(b1.x, b1.y);
                unsigned long long B11 = f2pack(b1.z, b1.w);
                float av[4] = {aq.x, aq.y, aq.z, aq.w};
                #pragma unroll
                for (int i = 0; i < 4; i++) {
                    unsigned long long A = f2pack(av[i], av[i]);
                    acc[i][0] = ffma2(A, B00, acc[i][0]);
                    acc[i][1] = ffma2(A, B01, acc[i][1]);
                    acc[i][2] = ffma2(A, B10, acc[i][2]);
                    acc[i][3] = ffma2(A, B11, acc[i][3]);
                }
            }
            // exp in registers, accumulate row partials, store exp'd to S
            #pragma unroll
            for (int i = 0; i < 4; i++) {
                int row = ty * 4 + i;
                float2 u0 = f2unpack(acc[i][0]);
                float2 u1 = f2unpack(acc[i][1]);
                float2 u2 = f2unpack(acc[i][2]);
                float2 u3 = f2unpack(acc[i][3]);
                float e0 = __expf(u0.x * 0.125f), e1 = __expf(u0.y * 0.125f);
                float e2 = __expf(u1.x * 0.125f), e3 = __expf(u1.y * 0.125f);
                float e4 = __expf(u2.x * 0.125f), e5 = __expf(u2.y * 0.125f);
                float e6 = __expf(u3.x * 0.125f), e7 = __expf(u3.y * 0.125f);
                rowpart[i] += ((e0 + e1) + (e2 + e3)) + ((e4 + e5) + (e6 + e7));
                *(float4*)&S[row * 1024 + k0 + 4 * tx]       = make_float4(e0, e1, e2, e3);
                *(float4*)&S[row * 1024 + k0 + 128 + 4 * tx] = make_float4(e4, e5, e6, e7);
            }
        }

        // row sums via shuffle (each warp's lanes hold same 4 rows), then one
        // float4 scale+accumulate pass into g_attn.
        #pragma unroll
        for (int i = 0; i < 4; i++) {
            float s = rowpart[i];
            #pragma unroll
            for (int o = 16; o; o >>= 1) s += __shfl_xor_sync(~0u, s, o);
            float inv = 1.f / s;
            int row = ty * 4 + i;
            const float4* Sv = (const float4*)&S[row * 1024];
            float4* gp = (float4*)(g_attn + ((size_t)(b * NN + q0 + row)) * NN);
            if (h == 0) {
                #pragma unroll
                for (int c = tx; c < 256; c += 32) {
                    float4 e = Sv[c];
                    gp[c] = make_float4(e.x * inv, e.y * inv, e.z * inv, e.w * inv);
                }
            } else {
                #pragma unroll
                for (int c = tx; c < 256; c += 32) {
                    float4 e = Sv[c];
                    float4 g = gp[c];
                    gp[c] = make_float4(fmaf(e.x, inv, g.x), fmaf(e.y, inv, g.y),
                                        fmaf(e.z, inv, g.z), fmaf(e.w, inv, g.w));
                }
            }
        }
    }
}

// ---------------------------------------------------------------------------
// Kernel 3a: w2 row sums.
// ---------------------------------------------------------------------------
__global__ __launch_bounds__(256) void rowsum_kernel() {
    int row  = blockIdx.x * 8 + (threadIdx.x >> 5);
    int lane = threadIdx.x & 31;
    const float* gp = g_attn + (size_t)row * NN;

    double s0 = 0.0, s1 = 0.0;
    #pragma unroll
    for (int c = 0; c < NN; c += 64) {
        float v0 = gp[c + lane];
        float v1 = gp[c + lane + 32];
        s0 += (double)exp_small_f(v0 * (1.f / 256.f));
        s1 += (double)exp_small_f(v1 * (1.f / 256.f));
    }
    double s = s0 + s1;
    #pragma unroll
    for (int o = 16; o; o >>= 1) s += __shfl_xor_sync(~0u, s, o);
    if (lane == 0) g_rinv[row] = 1.0 / s;
}

// ---------------------------------------------------------------------------
// Kernel 3b: column accumulation.  zero_ks split in two so attn is launch #4.
// ---------------------------------------------------------------------------
__global__ void zero_ks_kernel(int off) {
    g_ksc[off + blockIdx.x * 1024 + threadIdx.x] = 0.0;
}

__global__ __launch_bounds__(256) void colsum_kernel() {
    int b  = blockIdx.x >> 6;
    int q0 = (blockIdx.x & 63) << 4;
    int tid = threadIdx.x;
    const float* base = g_attn + ((size_t)b * NN + q0) * NN;
    const double* rinv = g_rinv + b * NN + q0;

    double acc[4] = {0.0, 0.0, 0.0, 0.0};
    #pragma unroll 4
    for (int q = 0; q < 16; q++) {
        const float* row = base + (size_t)q * NN;
        double inv = rinv[q];
        float e[4];
        #pragma unroll
        for (int j = 0; j < 4; j++) e[j] = exp_small_f(row[tid + j * 256] * (1.f / 256.f));
        #pragma unroll
        for (int j = 0; j < 4; j++) acc[j] = fma((double)e[j], inv, acc[j]);
    }
    #pragma unroll
    for (int j = 0; j < 4; j++)
        atomicAdd(&g_ksc[b * NN + tid + j * 256], acc[j] * (1.0 / 1024.0));
}

// ---------------------------------------------------------------------------
// Kernel 4: top-8 per batch, fp32-quantized compares + lowest-index ties.
// ---------------------------------------------------------------------------
__global__ __launch_bounds__(256) void topk_kernel(const float* __restrict__ x) {
    __shared__ float bvv[8];
    __shared__ int   bii[8];
    __shared__ int   sel[8];
    __shared__ int   sbi;
    int b = blockIdx.x;
    int tid = threadIdx.x;
    int lane = tid & 31, warp = tid >> 5;

    float v[4]; int idx[4];
    #pragma unroll
    for (int j = 0; j < 4; j++) {
        idx[j] = tid + j * 256;
        v[j] = (float)g_ksc[b * NN + idx[j]];
    }

    for (int it = 0; it < 8; it++) {
        float mv = v[0]; int mi = idx[0];
        #pragma unroll
        for (int j = 1; j < 4; j++)
            if (v[j] > mv || (v[j] == mv && idx[j] < mi)) { mv = v[j]; mi = idx[j]; }
        #pragma unroll
        for (int o = 16; o; o >>= 1) {
            float ov = __shfl_xor_sync(~0u, mv, o);
            int   oi = __shfl_xor_sync(~0u, mi, o);
            if (ov > mv || (ov == mv && oi < mi)) { mv = ov; mi = oi; }
        }
        if (lane == 0) { bvv[warp] = mv; bii[warp] = mi; }
        __syncthreads();
        if (tid == 0) {
            float m2 = bvv[0]; int i2 = bii[0];
            for (int w = 1; w < 8; w++)
                if (bvv[w] > m2 || (bvv[w] == m2 && bii[w] < i2)) { m2 = bvv[w]; i2 = bii[w]; }
            sel[it] = i2; sbi = i2;
        }
        __syncthreads();
        int si = sbi;
        #pragma unroll
        for (int j = 0; j < 4; j++) if (idx[j] == si) v[j] = -CUDART_INF_F;
        __syncthreads();
    }

    for (int c = tid; c < CC; c += 256) {
        const float* xb = x + ((size_t)(b * CC + c)) * NN;
        float m = -CUDART_INF_F;
        #pragma unroll
        for (int j = 0; j < 8; j++) m = fmaxf(m, xb[sel[j]]);
        g_mp[b * CC + c] = m;
    }
}

// ---------------------------------------------------------------------------
// Kernel 5: out = x + max_pooled broadcast (float4)
// ---------------------------------------------------------------------------
__global__ void add_kernel(const float* __restrict__ x, float* __restrict__ out) {
    int i = blockIdx.x * 256 + threadIdx.x;          // float4 index
    int bc = i >> 8;                                  // 256 float4 per (b,c) row
    float4 xv = ((const float4*)x)[i];
    float m = g_mp[bc];
    ((float4*)out)[i] = make_float4(xv.x + m, xv.y + m, xv.z + m, xv.w + m);
}

// ---------------------------------------------------------------------------
extern "C" void kernel_launch(void* const* d_in, const int* in_sizes, int n_in,
                              void* d_out, int out_size) {
    const float* x    = (const float*)d_in[0];
    const float* W    = (const float*)d_in[1];
    const float* bias = (const float*)d_in[2];
    float* out = (float*)d_out;

    cudaFuncSetAttribute(attn_kernel, cudaFuncAttributeMaxDynamicSharedMemorySize, SMEM2);

    zero_ks_kernel<<<4, 1024>>>(0);          // launch 1
    proj_kernel<<<dim3(16, 128), 256>>>(x, W, bias);  // launch 2
    zero_ks_kernel<<<4, 1024>>>(4096);       // launch 3
    attn_kernel<<<256, 256, SMEM2>>>();      // launch 4  (profiled)
    rowsum_kernel<<<1024, 256>>>();          // launch 5
    colsum_kernel<<<512, 256>>>();           // launch 6
    topk_kernel<<<8, 256>>>(x);              // launch 7
    add_kernel<<<(BB * CC * NN) / 1024, 256>>>(x, out);  // launch 8
}

// round 9
// speedup vs baseline: 1.8697x; 1.1645x over previous
#include <cuda_runtime.h>
#include <math_constants.h>

#define BB 8
#define CC 512
#define NN 1024
#define HH 8
#define DD 64

// Scratch (allocation-free: __device__ globals)
// Q/K stored d-major per (b,h):  g_q[((b*HH+h)*DD + d)*NN + n]
__device__ float  g_q[BB*HH*NN*DD];
__device__ float  g_k[BB*HH*NN*DD];
__device__ float  g_attn[BB*NN*NN];     // head-summed softmax rows (h=0..6 accum)
__device__ double g_ksc[BB*NN];         // key_scores accumulators (fp64)
__device__ float  g_mp[BB*CC];          // max-pooled (B, C)

// ---- packed f32x2 helpers ---------------------------------------------------
__device__ __forceinline__ unsigned long long f2pack(float lo, float hi) {
    unsigned long long r;
    asm("mov.b64 %0, {%1, %2};" : "=l"(r) : "f"(lo), "f"(hi));
    return r;
}
__device__ __forceinline__ unsigned long long ffma2(unsigned long long a,
                                                    unsigned long long b,
                                                    unsigned long long c) {
    unsigned long long d;
    asm("fma.rn.f32x2 %0, %1, %2, %3;" : "=l"(d) : "l"(a), "l"(b), "l"(c));
    return d;
}
__device__ __forceinline__ float2 f2unpack(unsigned long long v) {
    float lo, hi;
    asm("mov.b64 {%0, %1}, %2;" : "=f"(lo), "=f"(hi) : "l"(v));
    return make_float2(lo, hi);
}

// exp(x) for x in [0, 1/32], fp32 degree-4 Taylor (round-6 error budget).
__device__ __forceinline__ float exp_small_f(float x) {
    float p = 1.f / 24.f;
    p = fmaf(p, x, 1.f / 6.f);
    p = fmaf(p, x, 0.5f);
    p = fmaf(p, x, 1.f);
    p = fmaf(p, x, 1.f);
    return p;
}

// ---------------------------------------------------------------------------
// Kernel 1: fused Q/K projection. Tile 128m x 64j, 256 thr, microtile 8m x 4j.
// Output layout d-major: dst[((b*HH+head)*DD+dd)*NN + n].
// ---------------------------------------------------------------------------
__global__ __launch_bounds__(256) void proj_kernel(const float* __restrict__ x,
                                                   const float* __restrict__ W,
                                                   const float* __restrict__ bias) {
    __shared__ float As[16 * 132];   // [kk][128m], pad 132
    __shared__ float Bs[16 * 68];    // [kk][64j],  pad 68 (16B-aligned rows)
    int tid = threadIdx.x;
    int tx  = tid & 31;
    int wid = tid >> 5;
    int jq  = tx & 15;                 // j-quad: j = 4*jq
    int mg  = wid * 2 + (tx >> 4);     // m-group 0..15, rows mg*8..+7
    int j0 = blockIdx.x * 64;
    int m0 = blockIdx.y * 128;
    int b  = m0 >> 10;
    int n0 = m0 & 1023;
    const float* xb = x + (size_t)b * CC * NN;

    unsigned long long acc[4][4];
    #pragma unroll
    for (int i = 0; i < 4; i++)
        #pragma unroll
        for (int j = 0; j < 4; j++) acc[i][j] = 0ull;

    for (int kb = 0; kb < CC; kb += 16) {
        #pragma unroll
        for (int p = 0; p < 8; p++) {                 // As: 16k x 128m
            int e = tid + p * 256;
            int kk = e >> 7, mm = e & 127;
            As[kk * 132 + mm] = xb[(kb + kk) * NN + n0 + mm];
        }
        #pragma unroll
        for (int p = 0; p < 4; p++) {                 // Bs: 16k x 64j
            int e = tid + p * 256;
            int kk = e & 15, jl = e >> 4;
            Bs[kk * 68 + jl] = W[(size_t)(j0 + jl) * CC + kb + kk];
        }
        __syncthreads();
        #pragma unroll
        for (int kk = 0; kk < 16; kk++) {
            float4 a0 = *(const float4*)&As[kk * 132 + mg * 8];
            float4 a1 = *(const float4*)&As[kk * 132 + mg * 8 + 4];
            float4 bq = *(const float4*)&Bs[kk * 68 + 4 * jq];
            unsigned long long A[4] = { f2pack(a0.x, a0.y), f2pack(a0.z, a0.w),
                                        f2pack(a1.x, a1.y), f2pack(a1.z, a1.w) };
            unsigned long long Bd[4] = { f2pack(bq.x, bq.x), f2pack(bq.y, bq.y),
                                         f2pack(bq.z, bq.z), f2pack(bq.w, bq.w) };
            #pragma unroll
            for (int am = 0; am < 4; am++)
                #pragma unroll
                for (int j = 0; j < 4; j++)
                    acc[am][j] = ffma2(A[am], Bd[j], acc[am][j]);
        }
        __syncthreads();
    }

    // Epilogue: d-major stores, 2 float4 per j over the 8 m-rows.
    #pragma unroll
    for (int j = 0; j < 4; j++) {
        int jg = j0 + 4 * jq + j;
        float bsv = bias[jg];
        int head = (jg & 511) >> 6;
        int dd   = jg & 63;
        float* dst = ((jg < 512) ? g_q : g_k)
                   + ((size_t)(b * HH + head) * DD + dd) * NN + n0 + mg * 8;
        float2 u0 = f2unpack(acc[0][j]);
        float2 u1 = f2unpack(acc[1][j]);
        float2 u2 = f2unpack(acc[2][j]);
        float2 u3 = f2unpack(acc[3][j]);
        *(float4*)&dst[0] = make_float4(u0.x + bsv, u0.y + bsv, u1.x + bsv, u1.y + bsv);
        *(float4*)&dst[4] = make_float4(u2.x + bsv, u2.y + bsv, u3.x + bsv, u3.y + bsv);
    }
}

// ---------------------------------------------------------------------------
// Kernel 2: scores + per-head softmax + head accumulation; at h==7 fuses the
// whole w2 pipeline (rowsum + column accumulation into g_ksc).
// Block = (b, 32 q rows). Microtile 8q x 4k, packs along q. K/Q d-major.
// smem: Qs[64][36] + Ks[64][260] + S[32][1024] + rpart[64] + colsum[1024]d.
// ---------------------------------------------------------------------------
#define QS_STRIDE 36
#define KS_STRIDE 260
#define SM_QS   0
#define SM_KS   (64*QS_STRIDE)
#define SM_S    (SM_KS + 64*KS_STRIDE)
#define SM_RP   (SM_S + 32*1024)
#define SM_F32  (SM_RP + 64)            // total floats (colsum doubles after)
#define SMEM2   (SM_F32*4 + 1024*8)

__global__ __launch_bounds__(256) void attn_kernel() {
    extern __shared__ float sm[];
    float*  Qs     = sm + SM_QS;
    float*  Ks     = sm + SM_KS;
    float*  S      = sm + SM_S;
    float*  rpart  = sm + SM_RP;                 // [2][32] attn row-sum halves
    double* colsum = (double*)(sm + SM_F32);     // [1024]

    int tid = threadIdx.x;
    int b  = blockIdx.x >> 5;
    int q0 = (blockIdx.x & 31) << 5;
    int tx = tid & 31, ty = tid >> 5;
    int qg = (ty & 3) * 8;       // mainloop: 8 q-rows
    int kh = ty >> 2;            // mainloop: k-half (0/1) -> +kh*128

    for (int h = 0; h < HH; h++) {
        const float* Qg = g_q + (size_t)(b * HH + h) * DD * NN + q0;
        const float* Kg = g_k + (size_t)(b * HH + h) * DD * NN;

        __syncthreads();   // prev head's S consumed; Qs free
        #pragma unroll
        for (int it = 0; it < 2; it++) {         // Qs: 64d x 32q, float4
            int e = tid + it * 256;
            int dd = e >> 3, q4 = (e & 7) * 4;
            float4 v = *(const float4*)&Qg[(size_t)dd * NN + q4];
            *(float4*)&Qs[dd * QS_STRIDE + q4] = v;
        }
        if (h == 7) {                            // zero colsum (tile syncs cover)
            #pragma unroll
            for (int c = 0; c < 4; c++) colsum[tid * 4 + c] = 0.0;
        }

        float rowpart[8] = {0.f,0.f,0.f,0.f,0.f,0.f,0.f,0.f};

        for (int kt = 0; kt < 4; kt++) {
            int k0 = kt * 256;
            __syncthreads();
            #pragma unroll
            for (int it = 0; it < 16; it++) {    // Ks: 64d x 256k, float4
                int e = tid + it * 256;
                int dd = e >> 6, r4 = (e & 63) * 4;
                float4 v = *(const float4*)&Kg[(size_t)dd * NN + k0 + r4];
                *(float4*)&Ks[dd * KS_STRIDE + r4] = v;
            }
            __syncthreads();

            unsigned long long acc[4][4];
            #pragma unroll
            for (int i = 0; i < 4; i++)
                #pragma unroll
                for (int j = 0; j < 4; j++) acc[i][j] = 0ull;

            int kbase = kh * 128 + 4 * tx;
            #pragma unroll 8
            for (int kk = 0; kk < 64; kk++) {
                float4 a0 = *(const float4*)&Qs[kk * QS_STRIDE + qg];
                float4 a1 = *(const float4*)&Qs[kk * QS_STRIDE + qg + 4];
                float4 bv = *(const float4*)&Ks[kk * KS_STRIDE + kbase];
                unsigned long long A[4] = { f2pack(a0.x, a0.y), f2pack(a0.z, a0.w),
                                            f2pack(a1.x, a1.y), f2pack(a1.z, a1.w) };
                unsigned long long Bd[4] = { f2pack(bv.x, bv.x), f2pack(bv.y, bv.y),
                                             f2pack(bv.z, bv.z), f2pack(bv.w, bv.w) };
                #pragma unroll
                for (int qq = 0; qq < 4; qq++)
                    #pragma unroll
                    for (int kc = 0; kc < 4; kc++)
                        acc[qq][kc] = ffma2(A[qq], Bd[kc], acc[qq][kc]);
            }
            // exp in registers; rowparts; store exp'd to S
            #pragma unroll
            for (int qq = 0; qq < 4; qq++) {
                float2 u0 = f2unpack(acc[qq][0]);
                float2 u1 = f2unpack(acc[qq][1]);
                float2 u2 = f2unpack(acc[qq][2]);
                float2 u3 = f2unpack(acc[qq][3]);
                float4 lo = make_float4(__expf(u0.x * 0.125f), __expf(u1.x * 0.125f),
                                        __expf(u2.x * 0.125f), __expf(u3.x * 0.125f));
                float4 hi = make_float4(__expf(u0.y * 0.125f), __expf(u1.y * 0.125f),
                                        __expf(u2.y * 0.125f), __expf(u3.y * 0.125f));
                rowpart[2*qq]   += (lo.x + lo.y) + (lo.z + lo.w);
                rowpart[2*qq+1] += (hi.x + hi.y) + (hi.z + hi.w);
                *(float4*)&S[(qg + 2*qq)     * 1024 + k0 + kbase] = lo;
                *(float4*)&S[(qg + 2*qq + 1) * 1024 + k0 + kbase] = hi;
            }
        }

        // warp-half row sums -> rpart[kh][qg+i]
        #pragma unroll
        for (int i = 0; i < 8; i++) {
            float s = rowpart[i];
            #pragma unroll
            for (int o = 16; o; o >>= 1) s += __shfl_xor_sync(~0u, s, o);
            if (tx == 0) rpart[kh * 32 + qg + i] = s;
        }
        __syncthreads();   // rpart + all S stores visible

        // scale pass: warp ty owns rows ty*4..+3 over all 1024 cols
        if (h < 7) {
            #pragma unroll
            for (int r = 0; r < 4; r++) {
                int row = ty * 4 + r;
                float inv = 1.f / (rpart[row] + rpart[32 + row]);
                const float4* Sv = (const float4*)&S[row * 1024];
                float4* gp = (float4*)(g_attn + ((size_t)(b * NN + q0 + row)) * NN);
                if (h == 0) {
                    #pragma unroll
                    for (int j = 0; j < 8; j++) {
                        int c = tx + 32 * j;
                        float4 e = Sv[c];
                        gp[c] = make_float4(e.x*inv, e.y*inv, e.z*inv, e.w*inv);
                    }
                } else {
                    #pragma unroll
                    for (int j = 0; j < 8; j++) {
                        int c = tx + 32 * j;
                        float4 e = Sv[c];
                        float4 g = gp[c];
                        gp[c] = make_float4(fmaf(e.x,inv,g.x), fmaf(e.y,inv,g.y),
                                            fmaf(e.z,inv,g.z), fmaf(e.w,inv,g.w));
                    }
                }
            }
        } else {
            // fused w2: fin in regs -> exp_small -> fp64 rowsum -> column partials
            double colp[8][4];
            #pragma unroll
            for (int j = 0; j < 8; j++)
                #pragma unroll
                for (int c = 0; c < 4; c++) colp[j][c] = 0.0;

            #pragma unroll
            for (int r = 0; r < 4; r++) {
                int row = ty * 4 + r;
                float inv = 1.f / (rpart[row] + rpart[32 + row]);
                const float4* Sv = (const float4*)&S[row * 1024];
                const float4* gp = (const float4*)(g_attn + ((size_t)(b * NN + q0 + row)) * NN);
                float4 w2[8];
                double rs0 = 0.0, rs1 = 0.0, rs2 = 0.0, rs3 = 0.0;
                #pragma unroll
                for (int j = 0; j < 8; j++) {
                    int c = tx + 32 * j;
                    float4 e = Sv[c];
                    float4 g = gp[c];
                    float4 fin = make_float4(fmaf(e.x,inv,g.x), fmaf(e.y,inv,g.y),
                                             fmaf(e.z,inv,g.z), fmaf(e.w,inv,g.w));
                    float4 w = make_float4(exp_small_f(fin.x * (1.f/256.f)),
                                           exp_small_f(fin.y * (1.f/256.f)),
                                           exp_small_f(fin.z * (1.f/256.f)),
                                           exp_small_f(fin.w * (1.f/256.f)));
                    w2[j] = w;
                    rs0 += (double)w.x; rs1 += (double)w.y;
                    rs2 += (double)w.z; rs3 += (double)w.w;
                }
                double rs = (rs0 + rs1) + (rs2 + rs3);
                #pragma unroll
                for (int o = 16; o; o >>= 1) rs += __shfl_xor_sync(~0u, rs, o);
                double rinv = 1.0 / rs;
                #pragma unroll
                for (int j = 0; j < 8; j++) {
                    colp[j][0] = fma((double)w2[j].x, rinv, colp[j][0]);
                    colp[j][1] = fma((double)w2[j].y, rinv, colp[j][1]);
                    colp[j][2] = fma((double)w2[j].z, rinv, colp[j][2]);
                    colp[j][3] = fma((double)w2[j].w, rinv, colp[j][3]);
                }
            }
            // deterministic cross-warp combine (8 phases)
            for (int w = 0; w < 8; w++) {
                if (ty == w) {
                    #pragma unroll
                    for (int j = 0; j < 8; j++) {
                        int cb = 4 * (tx + 32 * j);
                        #pragma unroll
                        for (int c = 0; c < 4; c++) colsum[cb + c] += colp[j][c];
                    }
                }
                __syncthreads();
            }
            #pragma unroll
            for (int c = 0; c < 4; c++) {
                int k = tid * 4 + c;
                atomicAdd(&g_ksc[b * NN + k], colsum[k] * (1.0 / 1024.0));
            }
        }
    }
}

// ---------------------------------------------------------------------------
// Kernel 3: zero key_scores (split for launch ordering).
// ---------------------------------------------------------------------------
__global__ void zero_ks_kernel(int off) {
    g_ksc[off + blockIdx.x * 1024 + threadIdx.x] = 0.0;
}

// ---------------------------------------------------------------------------
// Kernel 4: top-8 per batch, fp32-quantized compares + lowest-index ties.
// ---------------------------------------------------------------------------
__global__ __launch_bounds__(256) void topk_kernel(const float* __restrict__ x) {
    __shared__ float bvv[8];
    __shared__ int   bii[8];
    __shared__ int   sel[8];
    __shared__ int   sbi;
    int b = blockIdx.x;
    int tid = threadIdx.x;
    int lane = tid & 31, warp = tid >> 5;

    float v[4]; int idx[4];
    #pragma unroll
    for (int j = 0; j < 4; j++) {
        idx[j] = tid + j * 256;
        v[j] = (float)g_ksc[b * NN + idx[j]];
    }

    for (int it = 0; it < 8; it++) {
        float mv = v[0]; int mi = idx[0];
        #pragma unroll
        for (int j = 1; j < 4; j++)
            if (v[j] > mv || (v[j] == mv && idx[j] < mi)) { mv = v[j]; mi = idx[j]; }
        #pragma unroll
        for (int o = 16; o; o >>= 1) {
            float ov = __shfl_xor_sync(~0u, mv, o);
            int   oi = __shfl_xor_sync(~0u, mi, o);
            if (ov > mv || (ov == mv && oi < mi)) { mv = ov; mi = oi; }
        }
        if (lane == 0) { bvv[warp] = mv; bii[warp] = mi; }
        __syncthreads();
        if (tid == 0) {
            float m2 = bvv[0]; int i2 = bii[0];
            for (int w = 1; w < 8; w++)
                if (bvv[w] > m2 || (bvv[w] == m2 && bii[w] < i2)) { m2 = bvv[w]; i2 = bii[w]; }
            sel[it] = i2; sbi = i2;
        }
        __syncthreads();
        int si = sbi;
        #pragma unroll
        for (int j = 0; j < 4; j++) if (idx[j] == si) v[j] = -CUDART_INF_F;
        __syncthreads();
    }

    for (int c = tid; c < CC; c += 256) {
        const float* xb = x + ((size_t)(b * CC + c)) * NN;
        float m = -CUDART_INF_F;
        #pragma unroll
        for (int j = 0; j < 8; j++) m = fmaxf(m, xb[sel[j]]);
        g_mp[b * CC + c] = m;
    }
}

// ---------------------------------------------------------------------------
// Kernel 5: out = x + max_pooled broadcast (float4)
// ---------------------------------------------------------------------------
__global__ void add_kernel(const float* __restrict__ x, float* __restrict__ out) {
    int i = blockIdx.x * 256 + threadIdx.x;
    int bc = i >> 8;
    float4 xv = ((const float4*)x)[i];
    float m = g_mp[bc];
    ((float4*)out)[i] = make_float4(xv.x + m, xv.y + m, xv.z + m, xv.w + m);
}

// ---------------------------------------------------------------------------
extern "C" void kernel_launch(void* const* d_in, const int* in_sizes, int n_in,
                              void* d_out, int out_size) {
    const float* x    = (const float*)d_in[0];
    const float* W    = (const float*)d_in[1];
    const float* bias = (const float*)d_in[2];
    float* out = (float*)d_out;

    cudaFuncSetAttribute(attn_kernel, cudaFuncAttributeMaxDynamicSharedMemorySize, SMEM2);

    zero_ks_kernel<<<4, 1024>>>(0);                    // launch 1
    zero_ks_kernel<<<4, 1024>>>(4096);                 // launch 2
    proj_kernel<<<dim3(16, 64), 256>>>(x, W, bias);    // launch 3
    attn_kernel<<<256, 256, SMEM2>>>();                // launch 4 (profiled)
    topk_kernel<<<8, 256>>>(x);                        // launch 5
    add_kernel<<<(BB * CC * NN) / 1024, 256>>>(x, out);// launch 6
}